// round 4
// baseline (speedup 1.0000x reference)
#include <cuda_runtime.h>
#include <stdint.h>

// FP32 bit-pulse -> FP8 E4M3 bit-pulse converter.
// Input : N*32 floats (0.0f/1.0f), row = [S, E7..E0, M22..M0] MSB first
// Output: N*8  floats, row = [S, E3..E0, M2..M0]
//
// Warp-cooperative smem nibble transpose (round-3 structure) + software
// pipelining: each warp processes several 32-row tiles in a grid-stride loop,
// and issues the NEXT tile's 8 coalesced LDG.128 before doing the current
// tile's smem-read/convert/store phase, keeping 8 reads in flight per warp
// continuously so the DRAM read queue never drains.

__device__ __forceinline__ void convert_row(uint32_t packed,
                                            float4& o0, float4& o1)
{
    uint32_t s    = packed >> 31;
    uint32_t exp  = (packed >> 23) & 0xFFu;
    uint32_t mant = packed & 0x7FFFFFu;

    // normal path: RNE round 23 -> 3 mantissa bits
    uint32_t kept = mant >> 20;
    uint32_t R    = (mant >> 19) & 1u;
    uint32_t S    = (mant & ((1u << 19) - 1u)) != 0u;
    uint32_t L    = kept & 1u;
    uint32_t mr   = kept + (R & (S | L));
    uint32_t carry = mr >> 3;
    uint32_t mant_norm = carry ? 0u : (mr & 7u);
    uint32_t exp_norm  = exp - 120u + carry;

    // subnormal path (117 <= exp <= 120)
    uint32_t full = (1u << 23) | mant;
    int shi = 141 - (int)exp;
    if (shi < 1)  shi = 1;
    if (shi > 24) shi = 24;
    uint32_t sh = (uint32_t)shi;
    uint32_t kept_s = full >> sh;
    uint32_t Rs = (full >> (sh - 1u)) & 1u;
    uint32_t Ss = (full & ((1u << (sh - 1u)) - 1u)) != 0u;
    uint32_t Ls = kept_s & 1u;
    uint32_t ms = kept_s + (Rs & (Ss | Ls));
    uint32_t sub_exp  = (ms >= 8u) ? 1u : 0u;
    uint32_t sub_mant = (ms >= 8u) ? 0u : ms;

    uint32_t exp8, mant8;
    if (exp > 134u)                      { exp8 = 15u;      mant8 = 6u;        }
    else if (exp >= 117u && exp <= 120u) { exp8 = sub_exp;  mant8 = sub_mant;  }
    else if (exp < 117u)                 { exp8 = 0u;       mant8 = 0u;        }
    else                                 { exp8 = exp_norm; mant8 = mant_norm; }

    o0.x = (float)s;
    o0.y = (float)((exp8 >> 3) & 1u);
    o0.z = (float)((exp8 >> 2) & 1u);
    o0.w = (float)((exp8 >> 1) & 1u);
    o1.x = (float)(exp8 & 1u);
    o1.y = (float)((mant8 >> 2) & 1u);
    o1.z = (float)((mant8 >> 1) & 1u);
    o1.w = (float)(mant8 & 1u);
}

__device__ __forceinline__ uint32_t nibble_of(uint4 v)
{
    return (((v.x >> 29) & 1u) << 3)
         | (((v.y >> 29) & 1u) << 2)
         | (((v.z >> 29) & 1u) << 1)
         |  ((v.w >> 29) & 1u);
}

__global__ __launch_bounds__(256) void fp32_to_fp8_pulse_kernel(
    const uint4* __restrict__ in,   // 8 x uint4 per row
    float4* __restrict__ out,       // 2 x float4 per row
    int nrows)
{
    __shared__ uint8_t snib[8][256];   // per-warp: 32 rows x 8 nibble-bytes

    const int warp      = threadIdx.x >> 5;
    const int lane      = threadIdx.x & 31;
    const int warpGlob  = blockIdx.x * 8 + warp;
    const int warpCount = gridDim.x * 8;
    const int nTiles    = nrows >> 5;        // full 32-row tiles

    int tile = warpGlob;
    if (tile < nTiles) {
        // prologue: load tile 0
        uint4 v[8];
        {
            const uint4* tp = in + (size_t)tile * 256;
#pragma unroll
            for (int p = 0; p < 8; p++) v[p] = tp[p * 32 + lane];
        }

        for (;;) {
            // stage nibbles (frees v for reuse)
#pragma unroll
            for (int p = 0; p < 8; p++)
                snib[warp][p * 32 + lane] = (uint8_t)nibble_of(v[p]);

            // issue next tile's loads BEFORE consuming this tile
            int nextTile = tile + warpCount;
            bool more = nextTile < nTiles;
            if (more) {
                const uint4* np = in + (size_t)nextTile * 256;
#pragma unroll
                for (int p = 0; p < 8; p++) v[p] = np[p * 32 + lane];
            }
            __syncwarp();

            // lane r: one LDS.64 fetches row r's 8 nibbles
            uint2 u = *reinterpret_cast<const uint2*>(&snib[warp][lane * 8]);

            uint32_t hi = ((u.x & 0x0000000Fu) << 28)
                        | ((u.x & 0x00000F00u) << 16)
                        | ((u.x & 0x000F0000u) << 4)
                        | ((u.x & 0x0F000000u) >> 8);
            uint32_t lo = ((u.y & 0x0000000Fu) << 12)
                        | ((u.y & 0x00000F00u) >> 0)
                        | ((u.y & 0x000F0000u) >> 12)
                        | ((u.y & 0x0F000000u) >> 24);
            uint32_t packed = hi | lo;

            float4 o0, o1;
            convert_row(packed, o0, o1);

            const int row = (tile << 5) + lane;
            out[(size_t)row * 2]     = o0;
            out[(size_t)row * 2 + 1] = o1;

            __syncwarp();             // snib safe to overwrite next iteration
            if (!more) break;
            tile = nextTile;
        }
    }

    // tail rows (nrows % 32), handled per-thread by global warp 0
    const int tailBase = nTiles << 5;
    if (warpGlob == 0) {
        for (int row = tailBase + lane; row < nrows; row += 32) {
            const uint4* p = in + (size_t)row * 8;
            uint32_t packed = 0;
#pragma unroll
            for (int k = 0; k < 8; k++)
                packed = (packed << 4) | nibble_of(p[k]);
            float4 o0, o1;
            convert_row(packed, o0, o1);
            out[(size_t)row * 2]     = o0;
            out[(size_t)row * 2 + 1] = o1;
        }
    }
}

extern "C" void kernel_launch(void* const* d_in, const int* in_sizes, int n_in,
                              void* d_out, int out_size)
{
    const uint4* in = (const uint4*)d_in[0];
    float4* out = (float4*)d_out;
    int nrows = in_sizes[0] / 32;

    int nTiles = nrows >> 5;
    int threads = 256;
    // ~4 tiles per warp for pipelining; cap grid so every warp loops.
    int blocks = (nTiles + 8 * 4 - 1) / (8 * 4);
    if (blocks < 1) blocks = 1;
    fp32_to_fp8_pulse_kernel<<<blocks, threads>>>(in, out, nrows);
}

// round 5
// speedup vs baseline: 1.0486x; 1.0486x over previous
#include <cuda_runtime.h>
#include <stdint.h>

// FP32 bit-pulse -> FP8 E4M3 bit-pulse converter.
// Input : N*32 floats (0.0f/1.0f), row = [S, E7..E0, M22..M0] MSB first
// Output: N*8  floats, row = [S, E3..E0, M2..M0]
//
// Round-3 structure (best measured): warp owns 32 consecutive rows, 8
// coalesced LDG.128, nibble-byte transpose through 2KB smem, one LDS.64 per
// lane, convert, 2x STG.128. This round adds streaming cache hints
// (__ldcs/__stcs): the 256MB input / 64MB output stream through L2 with zero
// reuse, so evict-first residency reduces L2 thrash and read/write turnaround.

__device__ __forceinline__ void convert_row(uint32_t packed,
                                            float4& o0, float4& o1)
{
    uint32_t s    = packed >> 31;
    uint32_t exp  = (packed >> 23) & 0xFFu;
    uint32_t mant = packed & 0x7FFFFFu;

    // normal path: RNE round 23 -> 3 mantissa bits
    uint32_t kept = mant >> 20;
    uint32_t R    = (mant >> 19) & 1u;
    uint32_t S    = (mant & ((1u << 19) - 1u)) != 0u;
    uint32_t L    = kept & 1u;
    uint32_t mr   = kept + (R & (S | L));
    uint32_t carry = mr >> 3;
    uint32_t mant_norm = carry ? 0u : (mr & 7u);
    uint32_t exp_norm  = exp - 120u + carry;

    // subnormal path (117 <= exp <= 120)
    uint32_t full = (1u << 23) | mant;
    int shi = 141 - (int)exp;
    if (shi < 1)  shi = 1;
    if (shi > 24) shi = 24;
    uint32_t sh = (uint32_t)shi;
    uint32_t kept_s = full >> sh;
    uint32_t Rs = (full >> (sh - 1u)) & 1u;
    uint32_t Ss = (full & ((1u << (sh - 1u)) - 1u)) != 0u;
    uint32_t Ls = kept_s & 1u;
    uint32_t ms = kept_s + (Rs & (Ss | Ls));
    uint32_t sub_exp  = (ms >= 8u) ? 1u : 0u;
    uint32_t sub_mant = (ms >= 8u) ? 0u : ms;

    uint32_t exp8, mant8;
    if (exp > 134u)                      { exp8 = 15u;      mant8 = 6u;        }
    else if (exp >= 117u && exp <= 120u) { exp8 = sub_exp;  mant8 = sub_mant;  }
    else if (exp < 117u)                 { exp8 = 0u;       mant8 = 0u;        }
    else                                 { exp8 = exp_norm; mant8 = mant_norm; }

    o0.x = (float)s;
    o0.y = (float)((exp8 >> 3) & 1u);
    o0.z = (float)((exp8 >> 2) & 1u);
    o0.w = (float)((exp8 >> 1) & 1u);
    o1.x = (float)(exp8 & 1u);
    o1.y = (float)((mant8 >> 2) & 1u);
    o1.z = (float)((mant8 >> 1) & 1u);
    o1.w = (float)(mant8 & 1u);
}

__device__ __forceinline__ uint32_t nibble_of(uint4 v)
{
    return (((v.x >> 29) & 1u) << 3)
         | (((v.y >> 29) & 1u) << 2)
         | (((v.z >> 29) & 1u) << 1)
         |  ((v.w >> 29) & 1u);
}

__global__ __launch_bounds__(256) void fp32_to_fp8_pulse_kernel(
    const uint4* __restrict__ in,   // 8 x uint4 per row
    float4* __restrict__ out,       // 2 x float4 per row
    int nrows)
{
    __shared__ uint8_t snib[8][256];   // per-warp: 32 rows x 8 nibble-bytes

    const int warp = threadIdx.x >> 5;
    const int lane = threadIdx.x & 31;
    const int baserow = (blockIdx.x * 8 + warp) * 32;
    if (baserow >= nrows) return;

    if (baserow + 32 <= nrows) {
        // ---- fast path: full 32-row tile ----
        const uint4* tile = in + (size_t)baserow * 8;

        // coalesced streaming loads; each lane stores one nibble-byte per pass.
#pragma unroll
        for (int p = 0; p < 8; p++) {
            uint4 v = __ldcs(&tile[p * 32 + lane]);
            snib[warp][p * 32 + lane] = (uint8_t)nibble_of(v);
        }
        __syncwarp();

        // lane r: one LDS.64 fetches row r's 8 nibbles (bytes 8r..8r+7)
        uint2 u = *reinterpret_cast<const uint2*>(&snib[warp][lane * 8]);

        uint32_t hi = ((u.x & 0x0000000Fu) << 28)
                    | ((u.x & 0x00000F00u) << 16)
                    | ((u.x & 0x000F0000u) << 4)
                    | ((u.x & 0x0F000000u) >> 8);
        uint32_t lo = ((u.y & 0x0000000Fu) << 12)
                    | ((u.y & 0x00000F00u) >> 0)
                    | ((u.y & 0x000F0000u) >> 12)
                    | ((u.y & 0x0F000000u) >> 24);
        uint32_t packed = hi | lo;

        float4 o0, o1;
        convert_row(packed, o0, o1);

        const int row = baserow + lane;
        __stcs(&out[(size_t)row * 2],     o0);
        __stcs(&out[(size_t)row * 2 + 1], o1);
    } else {
        // ---- tail path: per-thread row ----
        const int row = baserow + lane;
        if (row >= nrows) return;
        const uint4* p = in + (size_t)row * 8;
        uint32_t packed = 0;
#pragma unroll
        for (int k = 0; k < 8; k++)
            packed = (packed << 4) | nibble_of(__ldcs(&p[k]));
        float4 o0, o1;
        convert_row(packed, o0, o1);
        __stcs(&out[(size_t)row * 2],     o0);
        __stcs(&out[(size_t)row * 2 + 1], o1);
    }
}

extern "C" void kernel_launch(void* const* d_in, const int* in_sizes, int n_in,
                              void* d_out, int out_size)
{
    const uint4* in = (const uint4*)d_in[0];
    float4* out = (float4*)d_out;
    int nrows = in_sizes[0] / 32;

    int threads = 256;
    int blocks = (nrows + threads - 1) / threads;
    fp32_to_fp8_pulse_kernel<<<blocks, threads>>>(in, out, nrows);
}